// round 8
// baseline (speedup 1.0000x reference)
#include <cuda_runtime.h>
#include <math.h>
#include <cstdint>
#include <stdint.h>

#define T_TOKENS 4096
#define DMODEL   1024
#define DFFN     4096
#define NEXP     8
#define TOPK     2
#define NSLOTS   (T_TOKENS * TOPK)
#define MT_MAX   64

// ---- scratch (__device__ globals; allocation-free rule) ----
__device__ float g_h[(size_t)NSLOTS * DFFN];        // 128 MiB (tf32-rounded)
__device__ float g_xr[(size_t)T_TOKENS * DMODEL];   // 16 MiB  (tf32-rounded x)
__device__ int   g_tok[NSLOTS];
__device__ float g_gate[NSLOTS];
__device__ int   g_counts[NEXP];
__device__ int   g_cursor[NEXP];
__device__ int   g_off[NEXP + 1];
__device__ int   g_topi[T_TOKENS * TOPK];
__device__ float g_topg[T_TOKENS * TOPK];
__device__ int   g_done;

// ---------------------------------------------------------------------------
__device__ __forceinline__ uint32_t smem_u32(const void* p) {
    uint32_t a;
    asm("{ .reg .u64 t; cvta.to.shared.u64 t, %1; cvt.u32.u64 %0, t; }" : "=r"(a) : "l"(p));
    return a;
}
__device__ __forceinline__ void cp_async16u(uint32_t daddr, const float* src) {
    asm volatile("cp.async.cg.shared.global [%0], [%1], 16;\n" :: "r"(daddr), "l"(src));
}
#define CP_COMMIT() asm volatile("cp.async.commit_group;\n" ::: "memory")

__device__ __forceinline__ float round_tf32(float f) {
    uint32_t r;
    asm("cvt.rna.tf32.f32 %0, %1;" : "=r"(r) : "f"(f));
    return __uint_as_float(r);
}
__device__ __forceinline__ uint32_t f2tf32u(float f) {
    uint32_t r;
    asm("cvt.rna.tf32.f32 %0, %1;" : "=r"(r) : "f"(f));
    return r;
}

// ---------------------------------------------------------------------------
__global__ void reset_out(float4* out, int n4) {
    int idx = blockIdx.x * blockDim.x + threadIdx.x;
    float4 z = make_float4(0.f, 0.f, 0.f, 0.f);
    for (int i = idx; i < n4; i += gridDim.x * blockDim.x) out[i] = z;
}

// One warp per token: noisy top-2 router. Also writes tf32-rounded x to g_xr.
// Last block computes expert offsets.
__global__ void router_kernel(const float* __restrict__ x, const float* __restrict__ noise,
                              const float* __restrict__ Wg, const float* __restrict__ bg,
                              const float* __restrict__ Wn, const float* __restrict__ bn) {
    int gw = (blockIdx.x * blockDim.x + threadIdx.x) >> 5;
    int lane = threadIdx.x & 31;
    if (gw < T_TOKENS) {
        const float* xr = x + (size_t)gw * DMODEL;
        float* xo = g_xr + (size_t)gw * DMODEL;
        float lg[NEXP], ln[NEXP];
#pragma unroll
        for (int e = 0; e < NEXP; e++) { lg[e] = 0.f; ln[e] = 0.f; }
        for (int d = lane; d < DMODEL; d += 32) {
            float xv = xr[d];
            xo[d] = round_tf32(xv);             // fused tf32 pre-round of x
#pragma unroll
            for (int e = 0; e < NEXP; e++) {
                lg[e] += xv * Wg[d * NEXP + e];
                ln[e] += xv * Wn[d * NEXP + e];
            }
        }
#pragma unroll
        for (int o = 16; o > 0; o >>= 1) {
#pragma unroll
            for (int e = 0; e < NEXP; e++) {
                lg[e] += __shfl_xor_sync(0xffffffffu, lg[e], o);
                ln[e] += __shfl_xor_sync(0xffffffffu, ln[e], o);
            }
        }
        if (lane == 0) {
            float nv[NEXP];
#pragma unroll
            for (int e = 0; e < NEXP; e++) {
                float nl = ln[e] + bn[e];
                float sp = (nl > 20.f) ? nl : log1pf(expf(nl));
                nv[e] = lg[e] + bg[e] + noise[gw * NEXP + e] * sp;
            }
            int i0 = 0;
#pragma unroll
            for (int e = 1; e < NEXP; e++) if (nv[e] > nv[i0]) i0 = e;
            int i1 = (i0 == 0) ? 1 : 0;
#pragma unroll
            for (int e = 0; e < NEXP; e++) if (e != i0 && nv[e] > nv[i1]) i1 = e;
            float e1 = expf(nv[i1] - nv[i0]);
            float s = 1.f + e1;
            g_topi[gw * 2]     = i0;  g_topg[gw * 2]     = 1.f / s;
            g_topi[gw * 2 + 1] = i1;  g_topg[gw * 2 + 1] = e1 / s;
            atomicAdd(&g_counts[i0], 1);
            atomicAdd(&g_counts[i1], 1);
        }
    }
    __syncthreads();
    if (threadIdx.x == 0) {
        __threadfence();
        int prev = atomicAdd(&g_done, 1);
        if (prev == (int)gridDim.x - 1) {
            g_done = 0;
            __threadfence();
            int acc = 0;
            for (int e = 0; e < NEXP; e++) {
                g_off[e] = acc; g_cursor[e] = acc;
                acc += g_counts[e];
                g_counts[e] = 0;        // ready for next replay
            }
            g_off[NEXP] = acc;
        }
    }
}

__global__ void scatter_kernel() {
    int t = blockIdx.x * blockDim.x + threadIdx.x;
    if (t >= T_TOKENS) return;
#pragma unroll
    for (int k = 0; k < TOPK; k++) {
        int e = g_topi[t * 2 + k];
        int pos = atomicAdd(&g_cursor[e], 1);
        g_tok[pos]  = t;
        g_gate[pos] = g_topg[t * 2 + k];
    }
}

// ---------------------------------------------------------------------------
// Grouped GEMM: mma.sync.m16n8k8 tf32.
//   4 warps, warp tile 64x64, CTA tile 128x128x32.
//   Single-sync pipeline: 3 smem slots, 2 cp.async groups in flight.
//   PHASE 0: h = relu(gather(xr) @ W1 + b1)   K=1024, N=4096
//   PHASE 1: out += gate * (h @ W2 + b2)      K=4096, N=1024
#define BM 128
#define BN 128
#define BK 32
#define NSTG 3
#define LDB 136                               // floats; conflict-free B reads
#define A_BYTES   (BM * 128)                  // 16384 (128B swizzled rows)
#define B_BYTES   (BK * LDB * 4)              // 17408
#define STG_BYTES (A_BYTES + B_BYTES)         // 33792
#define SMEM_BIAS (NSTG * STG_BYTES)
#define SMEM_TOTAL (SMEM_BIAS + BN * 4)       // 101888 -> 2 CTAs/SM

__device__ __forceinline__ void mma_tf32(float* c, const uint32_t* a, const uint32_t* b) {
    asm volatile(
        "mma.sync.aligned.m16n8k8.row.col.f32.tf32.tf32.f32 "
        "{%0,%1,%2,%3}, {%4,%5,%6,%7}, {%8,%9}, {%0,%1,%2,%3};"
        : "+f"(c[0]), "+f"(c[1]), "+f"(c[2]), "+f"(c[3])
        : "r"(a[0]), "r"(a[1]), "r"(a[2]), "r"(a[3]), "r"(b[0]), "r"(b[1]));
}
__device__ __forceinline__ void ldsm_x4(uint32_t* r, uint32_t addr) {
    asm volatile("ldmatrix.sync.aligned.m8n8.x4.shared.b16 {%0,%1,%2,%3}, [%4];"
                 : "=r"(r[0]), "=r"(r[1]), "=r"(r[2]), "=r"(r[3]) : "r"(addr));
}

template <int PHASE>
__global__ __launch_bounds__(128, 2)
void moe_gemm_mma(const float* __restrict__ W1, const float* __restrict__ b1,
                  const float* __restrict__ W2, const float* __restrict__ b2,
                  float* __restrict__ out) {
    constexpr int K  = PHASE ? DFFN : DMODEL;
    constexpr int NN = PHASE ? DMODEL : DFFN;

    int e  = blockIdx.x >> 6;
    int mt = blockIdx.x & (MT_MAX - 1);
    int off0  = g_off[e];
    int count = g_off[e + 1] - off0;
    if (mt * BM >= count) return;
    int n0 = blockIdx.y * BN;

    extern __shared__ char smem[];
    uint32_t sb = smem_u32(smem);
    float* sBias = (float*)(smem + SMEM_BIAS);

    int tid  = threadIdx.x;
    int wid  = tid >> 5;
    int lane = tid & 31;
    int wm = wid & 1;              // 2 warps along M (64 rows)
    int wn = wid >> 1;             // 2 warps along N (64 cols)

    const float* bias = PHASE ? (b2 + e * DMODEL) : (b1 + e * DFFN);
    sBias[tid] = bias[n0 + tid];   // blockDim == BN == 128

    const float* Bsrc = PHASE ? (W2 + (size_t)e * DFFN * DMODEL)
                              : (W1 + (size_t)e * DMODEL * DFFN);

    // ---- per-thread cp.async assignments (128 threads) ----
    // A: 128 rows x 8 chunks(16B): off = row*128 + ((chunk ^ (row&7))<<4)
    int ac = tid & 7;
    const float* aP[8];
    uint32_t aDst[8];
#pragma unroll
    for (int i = 0; i < 8; i++) {
        int idx = tid + i * 128;
        int row = idx >> 3;
        int lr = mt * BM + row;
        if (lr >= count) lr = count - 1;
        int slot = off0 + lr;
        const float* base = PHASE ? (g_h + (size_t)slot * DFFN)
                                  : (g_xr + (size_t)g_tok[slot] * DMODEL);
        aP[i]  = base + ac * 4;
        aDst[i] = (uint32_t)(row * 128 + ((ac ^ (row & 7)) << 4));
    }

    const int nIter = K / BK;

    auto prefetch = [&](int s, int k0) {
        uint32_t ab = sb + s * STG_BYTES;
        uint32_t bb = ab + A_BYTES;
#pragma unroll
        for (int i = 0; i < 8; i++)
            cp_async16u(ab + aDst[i], aP[i] + k0);
#pragma unroll
        for (int i = 0; i < 8; i++) {            // B: 32 k-rows x 32 chunks
            int idx = tid + i * 128;
            int kr = idx >> 5, c = idx & 31;
            cp_async16u(bb + (uint32_t)(kr * (LDB * 4) + c * 16),
                        Bsrc + (size_t)(k0 + kr) * NN + n0 + c * 4);
        }
    };

    // Prologue: 2 groups in flight (slots 0, 1).
    prefetch(0, 0);           CP_COMMIT();
    prefetch(1, BK);          CP_COMMIT();

    float acc[4][8][4];
#pragma unroll
    for (int mi = 0; mi < 4; mi++)
#pragma unroll
        for (int nj = 0; nj < 8; nj++)
#pragma unroll
            for (int r = 0; r < 4; r++) acc[mi][nj][r] = 0.f;

    // per-lane fragment address components
    int lrow = (lane & 7) + (((lane >> 3) & 1) << 3);   // 0..15
    int lchv = lane >> 4;                                // chunk parity
    int btg  = lane & 3;                                 // B k within quad
    int bgq  = lane >> 2;                                // B n within n8

    for (int i = 0; i < nIter; i++) {
        // stage i is the oldest pending group
        if (i < nIter - 1) asm volatile("cp.async.wait_group 1;\n" ::: "memory");
        else               asm volatile("cp.async.wait_group 0;\n" ::: "memory");
        __syncthreads();     // all warps done reading slot (i-1)%NSTG; stage i visible

        // depth-2 lookahead into the slot consumed last iteration
        if (i + 2 < nIter) { prefetch((i + 2) % NSTG, (i + 2) * BK); CP_COMMIT(); }

        int s = i % NSTG;
        uint32_t aBase = sb + s * STG_BYTES;
        const float* Bs = (const float*)(smem + s * STG_BYTES + A_BYTES);

#pragma unroll
        for (int ks = 0; ks < 4; ks++) {
            uint32_t ra[4][4];
#pragma unroll
            for (int mi = 0; mi < 4; mi++) {
                int row = wm * 64 + mi * 16 + lrow;
                int chunk = 2 * ks + lchv;
                uint32_t addr = aBase + (uint32_t)(row * 128 + ((chunk ^ (row & 7)) << 4));
                ldsm_x4(ra[mi], addr);
            }
            uint32_t rb[8][2];
            const float* bp = Bs + (ks * 8 + btg) * LDB + wn * 64 + bgq;
#pragma unroll
            for (int nj = 0; nj < 8; nj++) {
                rb[nj][0] = f2tf32u(bp[nj * 8]);
                rb[nj][1] = f2tf32u(bp[nj * 8 + 4 * LDB]);
            }
#pragma unroll
            for (int mi = 0; mi < 4; mi++)
#pragma unroll
                for (int nj = 0; nj < 8; nj++)
                    mma_tf32(acc[mi][nj], ra[mi], rb[nj]);
        }
        // no trailing barrier: next iter's top sync protects slot reuse
    }

    // ---- epilogue straight from registers ----
    int g  = lane >> 2;
    int tg = lane & 3;
#pragma unroll
    for (int mi = 0; mi < 4; mi++) {
#pragma unroll
        for (int half = 0; half < 2; half++) {
            int lr = mt * BM + wm * 64 + mi * 16 + half * 8 + g;
            if (lr >= count) continue;
            int slot = off0 + lr;
            if (PHASE == 0) {
                float* hrow = g_h + (size_t)slot * DFFN + n0;
#pragma unroll
                for (int nj = 0; nj < 8; nj++) {
                    int cl = wn * 64 + nj * 8 + tg * 2;
                    float2 v;
                    v.x = round_tf32(fmaxf(acc[mi][nj][half * 2 + 0] + sBias[cl],     0.f));
                    v.y = round_tf32(fmaxf(acc[mi][nj][half * 2 + 1] + sBias[cl + 1], 0.f));
                    *(float2*)(hrow + cl) = v;
                }
            } else {
                float gate = g_gate[slot];
                float* orow = out + (size_t)g_tok[slot] * DMODEL + n0;
#pragma unroll
                for (int nj = 0; nj < 8; nj++) {
                    int cl = wn * 64 + nj * 8 + tg * 2;
                    float v0 = (acc[mi][nj][half * 2 + 0] + sBias[cl])     * gate;
                    float v1 = (acc[mi][nj][half * 2 + 1] + sBias[cl + 1]) * gate;
                    asm volatile("red.global.add.f32 [%0], %1;" :: "l"(orow + cl),     "f"(v0) : "memory");
                    asm volatile("red.global.add.f32 [%0], %1;" :: "l"(orow + cl + 1), "f"(v1) : "memory");
                }
            }
        }
    }
}

// ---------------------------------------------------------------------------
extern "C" void kernel_launch(void* const* d_in, const int* in_sizes, int n_in,
                              void* d_out, int out_size) {
    const float* x     = (const float*)d_in[0];
    const float* noise = (const float*)d_in[1];
    const float* Wg    = (const float*)d_in[2];
    const float* bg    = (const float*)d_in[3];
    const float* Wn    = (const float*)d_in[4];
    const float* bn    = (const float*)d_in[5];
    const float* W1    = (const float*)d_in[6];
    const float* b1    = (const float*)d_in[7];
    const float* W2    = (const float*)d_in[8];
    const float* b2    = (const float*)d_in[9];
    float* out = (float*)d_out;

    cudaFuncSetAttribute(moe_gemm_mma<0>, cudaFuncAttributeMaxDynamicSharedMemorySize, SMEM_TOTAL);
    cudaFuncSetAttribute(moe_gemm_mma<1>, cudaFuncAttributeMaxDynamicSharedMemorySize, SMEM_TOTAL);

    router_kernel<<<(T_TOKENS * 32) / 256, 256>>>(x, noise, Wg, bg, Wn, bn);   // 1 (+x round, +offsets)
    scatter_kernel<<<T_TOKENS / 256, 256>>>();                                 // 2
    reset_out<<<1024, 256>>>((float4*)out, out_size / 4);                      // 3
    moe_gemm_mma<0><<<dim3(NEXP * MT_MAX, DFFN / BN), 128, SMEM_TOTAL>>>(W1, b1, W2, b2, out);   // 4
    moe_gemm_mma<1><<<dim3(NEXP * MT_MAX, DMODEL / BN), 128, SMEM_TOTAL>>>(W1, b1, W2, b2, out); // 5
}

// round 9
// speedup vs baseline: 1.0344x; 1.0344x over previous
#include <cuda_runtime.h>
#include <math.h>
#include <cstdint>
#include <stdint.h>

#define T_TOKENS 4096
#define DMODEL   1024
#define DFFN     4096
#define NEXP     8
#define TOPK     2
#define NSLOTS   (T_TOKENS * TOPK)
#define MT_MAX   64
#define KSL2     4        // split-K factor for fc2

// ---- scratch (__device__ globals; allocation-free rule) ----
__device__ float g_h[(size_t)NSLOTS * DFFN];        // 128 MiB (tf32-rounded)
__device__ float g_xr[(size_t)T_TOKENS * DMODEL];   // 16 MiB  (tf32-rounded x)
__device__ int   g_tok[NSLOTS];
__device__ float g_gate[NSLOTS];
__device__ int   g_counts[NEXP];
__device__ int   g_cursor[NEXP];
__device__ int   g_off[NEXP + 1];
__device__ int   g_topi[T_TOKENS * TOPK];
__device__ float g_topg[T_TOKENS * TOPK];
__device__ int   g_done;

// ---------------------------------------------------------------------------
__device__ __forceinline__ uint32_t smem_u32(const void* p) {
    uint32_t a;
    asm("{ .reg .u64 t; cvta.to.shared.u64 t, %1; cvt.u32.u64 %0, t; }" : "=r"(a) : "l"(p));
    return a;
}
__device__ __forceinline__ void cp_async16u(uint32_t daddr, const float* src) {
    asm volatile("cp.async.cg.shared.global [%0], [%1], 16;\n" :: "r"(daddr), "l"(src));
}
#define CP_COMMIT() asm volatile("cp.async.commit_group;\n" ::: "memory")

__device__ __forceinline__ float round_tf32(float f) {
    uint32_t r;
    asm("cvt.rna.tf32.f32 %0, %1;" : "=r"(r) : "f"(f));
    return __uint_as_float(r);
}
__device__ __forceinline__ uint32_t f2tf32u(float f) {
    uint32_t r;
    asm("cvt.rna.tf32.f32 %0, %1;" : "=r"(r) : "f"(f));
    return r;
}

// ---------------------------------------------------------------------------
__global__ void reset_out(float4* out, int n4) {
    int idx = blockIdx.x * blockDim.x + threadIdx.x;
    float4 z = make_float4(0.f, 0.f, 0.f, 0.f);
    for (int i = idx; i < n4; i += gridDim.x * blockDim.x) out[i] = z;
}

// One warp per token: noisy top-2 router. Also writes tf32-rounded x to g_xr.
// Last block computes expert offsets.
__global__ void router_kernel(const float* __restrict__ x, const float* __restrict__ noise,
                              const float* __restrict__ Wg, const float* __restrict__ bg,
                              const float* __restrict__ Wn, const float* __restrict__ bn) {
    int gw = (blockIdx.x * blockDim.x + threadIdx.x) >> 5;
    int lane = threadIdx.x & 31;
    if (gw < T_TOKENS) {
        const float* xr = x + (size_t)gw * DMODEL;
        float* xo = g_xr + (size_t)gw * DMODEL;
        float lg[NEXP], ln[NEXP];
#pragma unroll
        for (int e = 0; e < NEXP; e++) { lg[e] = 0.f; ln[e] = 0.f; }
        for (int d = lane; d < DMODEL; d += 32) {
            float xv = xr[d];
            xo[d] = round_tf32(xv);             // fused tf32 pre-round of x
#pragma unroll
            for (int e = 0; e < NEXP; e++) {
                lg[e] += xv * Wg[d * NEXP + e];
                ln[e] += xv * Wn[d * NEXP + e];
            }
        }
#pragma unroll
        for (int o = 16; o > 0; o >>= 1) {
#pragma unroll
            for (int e = 0; e < NEXP; e++) {
                lg[e] += __shfl_xor_sync(0xffffffffu, lg[e], o);
                ln[e] += __shfl_xor_sync(0xffffffffu, ln[e], o);
            }
        }
        if (lane == 0) {
            float nv[NEXP];
#pragma unroll
            for (int e = 0; e < NEXP; e++) {
                float nl = ln[e] + bn[e];
                float sp = (nl > 20.f) ? nl : log1pf(expf(nl));
                nv[e] = lg[e] + bg[e] + noise[gw * NEXP + e] * sp;
            }
            int i0 = 0;
#pragma unroll
            for (int e = 1; e < NEXP; e++) if (nv[e] > nv[i0]) i0 = e;
            int i1 = (i0 == 0) ? 1 : 0;
#pragma unroll
            for (int e = 0; e < NEXP; e++) if (e != i0 && nv[e] > nv[i1]) i1 = e;
            float e1 = expf(nv[i1] - nv[i0]);
            float s = 1.f + e1;
            g_topi[gw * 2]     = i0;  g_topg[gw * 2]     = 1.f / s;
            g_topi[gw * 2 + 1] = i1;  g_topg[gw * 2 + 1] = e1 / s;
            atomicAdd(&g_counts[i0], 1);
            atomicAdd(&g_counts[i1], 1);
        }
    }
    __syncthreads();
    if (threadIdx.x == 0) {
        __threadfence();
        int prev = atomicAdd(&g_done, 1);
        if (prev == (int)gridDim.x - 1) {
            g_done = 0;
            __threadfence();
            int acc = 0;
            for (int e = 0; e < NEXP; e++) {
                g_off[e] = acc; g_cursor[e] = acc;
                acc += g_counts[e];
                g_counts[e] = 0;        // ready for next replay
            }
            g_off[NEXP] = acc;
        }
    }
}

__global__ void scatter_kernel() {
    int t = blockIdx.x * blockDim.x + threadIdx.x;
    if (t >= T_TOKENS) return;
#pragma unroll
    for (int k = 0; k < TOPK; k++) {
        int e = g_topi[t * 2 + k];
        int pos = atomicAdd(&g_cursor[e], 1);
        g_tok[pos]  = t;
        g_gate[pos] = g_topg[t * 2 + k];
    }
}

// ---------------------------------------------------------------------------
// Grouped GEMM: mma.sync.m16n8k8 tf32.
//   4 warps, warp tile 64x64, CTA tile 128x128x32, NSTG=3 cp.async ring
//   (R7 double-sync mainloop — measured best).
//   PHASE 0: h = relu(gather(xr) @ W1 + b1)          K=1024, grid.z=1
//   PHASE 1: out += gate * (h @ W2 + b2), split-K=4  K=4096, grid.z=4
#define BM 128
#define BN 128
#define BK 32
#define NSTG 3
#define LDB 136                               // floats; conflict-free B reads
#define A_BYTES   (BM * 128)                  // 16384 (128B swizzled rows)
#define B_BYTES   (BK * LDB * 4)              // 17408
#define STG_BYTES (A_BYTES + B_BYTES)         // 33792
#define SMEM_BIAS (NSTG * STG_BYTES)
#define SMEM_TOTAL (SMEM_BIAS + BN * 4)       // 101888 -> 2 CTAs/SM

__device__ __forceinline__ void mma_tf32(float* c, const uint32_t* a, const uint32_t* b) {
    asm volatile(
        "mma.sync.aligned.m16n8k8.row.col.f32.tf32.tf32.f32 "
        "{%0,%1,%2,%3}, {%4,%5,%6,%7}, {%8,%9}, {%0,%1,%2,%3};"
        : "+f"(c[0]), "+f"(c[1]), "+f"(c[2]), "+f"(c[3])
        : "r"(a[0]), "r"(a[1]), "r"(a[2]), "r"(a[3]), "r"(b[0]), "r"(b[1]));
}
__device__ __forceinline__ void ldsm_x4(uint32_t* r, uint32_t addr) {
    asm volatile("ldmatrix.sync.aligned.m8n8.x4.shared.b16 {%0,%1,%2,%3}, [%4];"
                 : "=r"(r[0]), "=r"(r[1]), "=r"(r[2]), "=r"(r[3]) : "r"(addr));
}

template <int PHASE>
__global__ __launch_bounds__(128, 2)
void moe_gemm_mma(const float* __restrict__ W1, const float* __restrict__ b1,
                  const float* __restrict__ W2, const float* __restrict__ b2,
                  float* __restrict__ out) {
    constexpr int K  = PHASE ? DFFN : DMODEL;
    constexpr int NN = PHASE ? DMODEL : DFFN;
    constexpr int KSL = PHASE ? KSL2 : 1;
    constexpr int KPER = K / KSL;

    int e  = blockIdx.x >> 6;
    int mt = blockIdx.x & (MT_MAX - 1);
    int off0  = g_off[e];
    int count = g_off[e + 1] - off0;
    if (mt * BM >= count) return;
    int n0 = blockIdx.y * BN;
    int kz = (KSL > 1) ? blockIdx.z : 0;
    int k0base = kz * KPER;

    extern __shared__ char smem[];
    uint32_t sb = smem_u32(smem);
    float* sBias = (float*)(smem + SMEM_BIAS);

    int tid  = threadIdx.x;
    int wid  = tid >> 5;
    int lane = tid & 31;
    int wm = wid & 1;              // 2 warps along M (64 rows)
    int wn = wid >> 1;             // 2 warps along N (64 cols)

    const float* bias = PHASE ? (b2 + e * DMODEL) : (b1 + e * DFFN);
    sBias[tid] = (kz == 0) ? bias[n0 + tid] : 0.f;   // bias only from k-slice 0

    const float* Bsrc = PHASE ? (W2 + (size_t)e * DFFN * DMODEL)
                              : (W1 + (size_t)e * DMODEL * DFFN);

    // ---- per-thread cp.async assignments (128 threads) ----
    // A: 128 rows x 8 chunks(16B): off = row*128 + ((chunk ^ (row&7))<<4)
    int ac = tid & 7;
    const float* aP[8];
    uint32_t aDst[8];
#pragma unroll
    for (int i = 0; i < 8; i++) {
        int idx = tid + i * 128;
        int row = idx >> 3;
        int lr = mt * BM + row;
        if (lr >= count) lr = count - 1;
        int slot = off0 + lr;
        const float* base = PHASE ? (g_h + (size_t)slot * DFFN)
                                  : (g_xr + (size_t)g_tok[slot] * DMODEL);
        aP[i]  = base + ac * 4;
        aDst[i] = (uint32_t)(row * 128 + ((ac ^ (row & 7)) << 4));
    }

    const int nIter = KPER / BK;

    auto prefetch = [&](int s, int k0) {
        uint32_t ab = sb + s * STG_BYTES;
        uint32_t bb = ab + A_BYTES;
#pragma unroll
        for (int i = 0; i < 8; i++)
            cp_async16u(ab + aDst[i], aP[i] + k0);
#pragma unroll
        for (int i = 0; i < 8; i++) {            // B: 32 k-rows x 32 chunks
            int idx = tid + i * 128;
            int kr = idx >> 5, c = idx & 31;
            cp_async16u(bb + (uint32_t)(kr * (LDB * 4) + c * 16),
                        Bsrc + (size_t)(k0 + kr) * NN + n0 + c * 4);
        }
    };

#pragma unroll
    for (int p = 0; p < NSTG; p++) { prefetch(p, k0base + p * BK); CP_COMMIT(); }

    float acc[4][8][4];
#pragma unroll
    for (int mi = 0; mi < 4; mi++)
#pragma unroll
        for (int nj = 0; nj < 8; nj++)
#pragma unroll
            for (int r = 0; r < 4; r++) acc[mi][nj][r] = 0.f;

    // per-lane fragment address components
    int lrow = (lane & 7) + (((lane >> 3) & 1) << 3);   // 0..15
    int lchv = lane >> 4;                                // chunk parity
    int btg  = lane & 3;                                 // B k within quad
    int bgq  = lane >> 2;                                // B n within n8

    for (int i = 0; i < nIter; i++) {
        // stage i must be complete at top of iter i (tail-correct)
        int rem = nIter - 1 - i;
        if (rem >= NSTG - 1)      asm volatile("cp.async.wait_group 2;\n" ::: "memory");
        else if (rem == 1)        asm volatile("cp.async.wait_group 1;\n" ::: "memory");
        else                      asm volatile("cp.async.wait_group 0;\n" ::: "memory");
        __syncthreads();
        int s = i % NSTG;
        uint32_t aBase = sb + s * STG_BYTES;
        const float* Bs = (const float*)(smem + s * STG_BYTES + A_BYTES);

#pragma unroll
        for (int ks = 0; ks < 4; ks++) {
            uint32_t ra[4][4];
#pragma unroll
            for (int mi = 0; mi < 4; mi++) {
                int row = wm * 64 + mi * 16 + lrow;
                int chunk = 2 * ks + lchv;
                uint32_t addr = aBase + (uint32_t)(row * 128 + ((chunk ^ (row & 7)) << 4));
                ldsm_x4(ra[mi], addr);
            }
            uint32_t rb[8][2];
            const float* bp = Bs + (ks * 8 + btg) * LDB + wn * 64 + bgq;
#pragma unroll
            for (int nj = 0; nj < 8; nj++) {
                rb[nj][0] = f2tf32u(bp[nj * 8]);
                rb[nj][1] = f2tf32u(bp[nj * 8 + 4 * LDB]);
            }
#pragma unroll
            for (int mi = 0; mi < 4; mi++)
#pragma unroll
                for (int nj = 0; nj < 8; nj++)
                    mma_tf32(acc[mi][nj], ra[mi], rb[nj]);
        }
        __syncthreads();
        if (i + NSTG < nIter) { prefetch(s, k0base + (i + NSTG) * BK); CP_COMMIT(); }
    }

    // ---- epilogue straight from registers ----
    int g  = lane >> 2;
    int tg = lane & 3;
#pragma unroll
    for (int mi = 0; mi < 4; mi++) {
#pragma unroll
        for (int half = 0; half < 2; half++) {
            int lr = mt * BM + wm * 64 + mi * 16 + half * 8 + g;
            if (lr >= count) continue;
            int slot = off0 + lr;
            if (PHASE == 0) {
                float* hrow = g_h + (size_t)slot * DFFN + n0;
#pragma unroll
                for (int nj = 0; nj < 8; nj++) {
                    int cl = wn * 64 + nj * 8 + tg * 2;
                    float2 v;
                    v.x = round_tf32(fmaxf(acc[mi][nj][half * 2 + 0] + sBias[cl],     0.f));
                    v.y = round_tf32(fmaxf(acc[mi][nj][half * 2 + 1] + sBias[cl + 1], 0.f));
                    *(float2*)(hrow + cl) = v;
                }
            } else {
                float gate = g_gate[slot];
                float* orow = out + (size_t)g_tok[slot] * DMODEL + n0;
#pragma unroll
                for (int nj = 0; nj < 8; nj++) {
                    int cl = wn * 64 + nj * 8 + tg * 2;
                    float v0 = (acc[mi][nj][half * 2 + 0] + sBias[cl])     * gate;
                    float v1 = (acc[mi][nj][half * 2 + 1] + sBias[cl + 1]) * gate;
                    asm volatile("red.global.add.f32 [%0], %1;" :: "l"(orow + cl),     "f"(v0) : "memory");
                    asm volatile("red.global.add.f32 [%0], %1;" :: "l"(orow + cl + 1), "f"(v1) : "memory");
                }
            }
        }
    }
}

// ---------------------------------------------------------------------------
extern "C" void kernel_launch(void* const* d_in, const int* in_sizes, int n_in,
                              void* d_out, int out_size) {
    const float* x     = (const float*)d_in[0];
    const float* noise = (const float*)d_in[1];
    const float* Wg    = (const float*)d_in[2];
    const float* bg    = (const float*)d_in[3];
    const float* Wn    = (const float*)d_in[4];
    const float* bn    = (const float*)d_in[5];
    const float* W1    = (const float*)d_in[6];
    const float* b1    = (const float*)d_in[7];
    const float* W2    = (const float*)d_in[8];
    const float* b2    = (const float*)d_in[9];
    float* out = (float*)d_out;

    cudaFuncSetAttribute(moe_gemm_mma<0>, cudaFuncAttributeMaxDynamicSharedMemorySize, SMEM_TOTAL);
    cudaFuncSetAttribute(moe_gemm_mma<1>, cudaFuncAttributeMaxDynamicSharedMemorySize, SMEM_TOTAL);

    router_kernel<<<(T_TOKENS * 32) / 256, 256>>>(x, noise, Wg, bg, Wn, bn);   // 1 (+x round, +offsets)
    scatter_kernel<<<T_TOKENS / 256, 256>>>();                                 // 2
    reset_out<<<1024, 256>>>((float4*)out, out_size / 4);                      // 3
    moe_gemm_mma<0><<<dim3(NEXP * MT_MAX, DFFN / BN, 1), 128, SMEM_TOTAL>>>(W1, b1, W2, b2, out);      // 4
    moe_gemm_mma<1><<<dim3(NEXP * MT_MAX, DMODEL / BN, KSL2), 128, SMEM_TOTAL>>>(W1, b1, W2, b2, out); // 5
}

// round 10
// speedup vs baseline: 1.0345x; 1.0000x over previous
#include <cuda_runtime.h>
#include <math.h>
#include <cstdint>
#include <stdint.h>

#define T_TOKENS 4096
#define DMODEL   1024
#define DFFN     4096
#define NEXP     8
#define TOPK     2
#define NSLOTS   (T_TOKENS * TOPK)
#define MT_MAX   64
#define KSL2     4        // split-K factor for fc2

// ---- scratch (__device__ globals; allocation-free rule) ----
__device__ float g_h[(size_t)NSLOTS * DFFN];        // 128 MiB (tf32-rounded)
__device__ float g_xr[(size_t)T_TOKENS * DMODEL];   // 16 MiB  (tf32-rounded x)
__device__ int   g_tok[NSLOTS];
__device__ float g_gate[NSLOTS];
__device__ int   g_counts[NEXP];
__device__ int   g_cursor[NEXP];
__device__ int   g_off[NEXP + 1];
__device__ int   g_topi[T_TOKENS * TOPK];
__device__ float g_topg[T_TOKENS * TOPK];
__device__ int   g_done;

// ---------------------------------------------------------------------------
__device__ __forceinline__ uint32_t smem_u32(const void* p) {
    uint32_t a;
    asm("{ .reg .u64 t; cvta.to.shared.u64 t, %1; cvt.u32.u64 %0, t; }" : "=r"(a) : "l"(p));
    return a;
}
__device__ __forceinline__ void cp_async16u(uint32_t daddr, const float* src) {
    asm volatile("cp.async.cg.shared.global [%0], [%1], 16;\n" :: "r"(daddr), "l"(src));
}
#define CP_COMMIT() asm volatile("cp.async.commit_group;\n" ::: "memory")

__device__ __forceinline__ float round_tf32(float f) {
    uint32_t r;
    asm("cvt.rna.tf32.f32 %0, %1;" : "=r"(r) : "f"(f));
    return __uint_as_float(r);
}
__device__ __forceinline__ uint32_t f2tf32u(float f) {
    uint32_t r;
    asm("cvt.rna.tf32.f32 %0, %1;" : "=r"(r) : "f"(f));
    return r;
}

// ---------------------------------------------------------------------------
__global__ void reset_out(float4* out, int n4) {
    int idx = blockIdx.x * blockDim.x + threadIdx.x;
    float4 z = make_float4(0.f, 0.f, 0.f, 0.f);
    for (int i = idx; i < n4; i += gridDim.x * blockDim.x) out[i] = z;
}

// One warp per token: noisy top-2 router. Also writes tf32-rounded x to g_xr.
// Last block computes expert offsets.
__global__ void router_kernel(const float* __restrict__ x, const float* __restrict__ noise,
                              const float* __restrict__ Wg, const float* __restrict__ bg,
                              const float* __restrict__ Wn, const float* __restrict__ bn) {
    int gw = (blockIdx.x * blockDim.x + threadIdx.x) >> 5;
    int lane = threadIdx.x & 31;
    if (gw < T_TOKENS) {
        const float* xr = x + (size_t)gw * DMODEL;
        float* xo = g_xr + (size_t)gw * DMODEL;
        float lg[NEXP], ln[NEXP];
#pragma unroll
        for (int e = 0; e < NEXP; e++) { lg[e] = 0.f; ln[e] = 0.f; }
        for (int d = lane; d < DMODEL; d += 32) {
            float xv = xr[d];
            xo[d] = round_tf32(xv);             // fused tf32 pre-round of x
#pragma unroll
            for (int e = 0; e < NEXP; e++) {
                lg[e] += xv * Wg[d * NEXP + e];
                ln[e] += xv * Wn[d * NEXP + e];
            }
        }
#pragma unroll
        for (int o = 16; o > 0; o >>= 1) {
#pragma unroll
            for (int e = 0; e < NEXP; e++) {
                lg[e] += __shfl_xor_sync(0xffffffffu, lg[e], o);
                ln[e] += __shfl_xor_sync(0xffffffffu, ln[e], o);
            }
        }
        if (lane == 0) {
            float nv[NEXP];
#pragma unroll
            for (int e = 0; e < NEXP; e++) {
                float nl = ln[e] + bn[e];
                float sp = (nl > 20.f) ? nl : log1pf(expf(nl));
                nv[e] = lg[e] + bg[e] + noise[gw * NEXP + e] * sp;
            }
            int i0 = 0;
#pragma unroll
            for (int e = 1; e < NEXP; e++) if (nv[e] > nv[i0]) i0 = e;
            int i1 = (i0 == 0) ? 1 : 0;
#pragma unroll
            for (int e = 0; e < NEXP; e++) if (e != i0 && nv[e] > nv[i1]) i1 = e;
            float e1 = expf(nv[i1] - nv[i0]);
            float s = 1.f + e1;
            g_topi[gw * 2]     = i0;  g_topg[gw * 2]     = 1.f / s;
            g_topi[gw * 2 + 1] = i1;  g_topg[gw * 2 + 1] = e1 / s;
            atomicAdd(&g_counts[i0], 1);
            atomicAdd(&g_counts[i1], 1);
        }
    }
    __syncthreads();
    if (threadIdx.x == 0) {
        __threadfence();
        int prev = atomicAdd(&g_done, 1);
        if (prev == (int)gridDim.x - 1) {
            g_done = 0;
            __threadfence();
            int acc = 0;
            for (int e = 0; e < NEXP; e++) {
                g_off[e] = acc; g_cursor[e] = acc;
                acc += g_counts[e];
                g_counts[e] = 0;        // ready for next replay
            }
            g_off[NEXP] = acc;
        }
    }
}

__global__ void scatter_kernel() {
    int t = blockIdx.x * blockDim.x + threadIdx.x;
    if (t >= T_TOKENS) return;
#pragma unroll
    for (int k = 0; k < TOPK; k++) {
        int e = g_topi[t * 2 + k];
        int pos = atomicAdd(&g_cursor[e], 1);
        g_tok[pos]  = t;
        g_gate[pos] = g_topg[t * 2 + k];
    }
}

// ---------------------------------------------------------------------------
// Grouped GEMM: mma.sync.m16n8k8 tf32.
//   4 warps, warp tile 64x64, CTA tile 128x128x32, NSTG=3 cp.async ring
//   (double-sync mainloop) + rb double-buffer: B fragment loads for ks+1
//   retire under the mma stream of ks.
//   PHASE 0: h = relu(gather(xr) @ W1 + b1)          K=1024, grid.z=1
//   PHASE 1: out += gate * (h @ W2 + b2), split-K=4  K=4096, grid.z=4
#define BM 128
#define BN 128
#define BK 32
#define NSTG 3
#define LDB 136                               // floats; conflict-free B reads
#define A_BYTES   (BM * 128)                  // 16384 (128B swizzled rows)
#define B_BYTES   (BK * LDB * 4)              // 17408
#define STG_BYTES (A_BYTES + B_BYTES)         // 33792
#define SMEM_BIAS (NSTG * STG_BYTES)
#define SMEM_TOTAL (SMEM_BIAS + BN * 4)       // 101888 -> 2 CTAs/SM

__device__ __forceinline__ void mma_tf32(float* c, const uint32_t* a, const uint32_t* b) {
    asm volatile(
        "mma.sync.aligned.m16n8k8.row.col.f32.tf32.tf32.f32 "
        "{%0,%1,%2,%3}, {%4,%5,%6,%7}, {%8,%9}, {%0,%1,%2,%3};"
        : "+f"(c[0]), "+f"(c[1]), "+f"(c[2]), "+f"(c[3])
        : "r"(a[0]), "r"(a[1]), "r"(a[2]), "r"(a[3]), "r"(b[0]), "r"(b[1]));
}
__device__ __forceinline__ void ldsm_x4(uint32_t* r, uint32_t addr) {
    asm volatile("ldmatrix.sync.aligned.m8n8.x4.shared.b16 {%0,%1,%2,%3}, [%4];"
                 : "=r"(r[0]), "=r"(r[1]), "=r"(r[2]), "=r"(r[3]) : "r"(addr));
}

template <int PHASE>
__global__ __launch_bounds__(128, 2)
void moe_gemm_mma(const float* __restrict__ W1, const float* __restrict__ b1,
                  const float* __restrict__ W2, const float* __restrict__ b2,
                  float* __restrict__ out) {
    constexpr int K  = PHASE ? DFFN : DMODEL;
    constexpr int NN = PHASE ? DMODEL : DFFN;
    constexpr int KSL = PHASE ? KSL2 : 1;
    constexpr int KPER = K / KSL;

    int e  = blockIdx.x >> 6;
    int mt = blockIdx.x & (MT_MAX - 1);
    int off0  = g_off[e];
    int count = g_off[e + 1] - off0;
    if (mt * BM >= count) return;
    int n0 = blockIdx.y * BN;
    int kz = (KSL > 1) ? blockIdx.z : 0;
    int k0base = kz * KPER;

    extern __shared__ char smem[];
    uint32_t sb = smem_u32(smem);
    float* sBias = (float*)(smem + SMEM_BIAS);

    int tid  = threadIdx.x;
    int wid  = tid >> 5;
    int lane = tid & 31;
    int wm = wid & 1;              // 2 warps along M (64 rows)
    int wn = wid >> 1;             // 2 warps along N (64 cols)

    const float* bias = PHASE ? (b2 + e * DMODEL) : (b1 + e * DFFN);
    sBias[tid] = (kz == 0) ? bias[n0 + tid] : 0.f;   // bias only from k-slice 0

    const float* Bsrc = PHASE ? (W2 + (size_t)e * DFFN * DMODEL)
                              : (W1 + (size_t)e * DMODEL * DFFN);

    // ---- per-thread cp.async assignments (128 threads) ----
    int ac = tid & 7;
    const float* aP[8];
    uint32_t aDst[8];
#pragma unroll
    for (int i = 0; i < 8; i++) {
        int idx = tid + i * 128;
        int row = idx >> 3;
        int lr = mt * BM + row;
        if (lr >= count) lr = count - 1;
        int slot = off0 + lr;
        const float* base = PHASE ? (g_h + (size_t)slot * DFFN)
                                  : (g_xr + (size_t)g_tok[slot] * DMODEL);
        aP[i]  = base + ac * 4;
        aDst[i] = (uint32_t)(row * 128 + ((ac ^ (row & 7)) << 4));
    }

    const int nIter = KPER / BK;

    auto prefetch = [&](int s, int k0) {
        uint32_t ab = sb + s * STG_BYTES;
        uint32_t bb = ab + A_BYTES;
#pragma unroll
        for (int i = 0; i < 8; i++)
            cp_async16u(ab + aDst[i], aP[i] + k0);
#pragma unroll
        for (int i = 0; i < 8; i++) {            // B: 32 k-rows x 32 chunks
            int idx = tid + i * 128;
            int kr = idx >> 5, c = idx & 31;
            cp_async16u(bb + (uint32_t)(kr * (LDB * 4) + c * 16),
                        Bsrc + (size_t)(k0 + kr) * NN + n0 + c * 4);
        }
    };

#pragma unroll
    for (int p = 0; p < NSTG; p++) { prefetch(p, k0base + p * BK); CP_COMMIT(); }

    float acc[4][8][4];
#pragma unroll
    for (int mi = 0; mi < 4; mi++)
#pragma unroll
        for (int nj = 0; nj < 8; nj++)
#pragma unroll
            for (int r = 0; r < 4; r++) acc[mi][nj][r] = 0.f;

    // per-lane fragment address components
    int lrow = (lane & 7) + (((lane >> 3) & 1) << 3);   // 0..15
    int lchv = lane >> 4;                                // chunk parity
    int btg  = lane & 3;                                 // B k within quad
    int bgq  = lane >> 2;                                // B n within n8

    for (int i = 0; i < nIter; i++) {
        int rem = nIter - 1 - i;
        if (rem >= NSTG - 1)      asm volatile("cp.async.wait_group 2;\n" ::: "memory");
        else if (rem == 1)        asm volatile("cp.async.wait_group 1;\n" ::: "memory");
        else                      asm volatile("cp.async.wait_group 0;\n" ::: "memory");
        __syncthreads();
        int s = i % NSTG;
        uint32_t aBase = sb + s * STG_BYTES;
        const float* Bs = (const float*)(smem + s * STG_BYTES + A_BYTES);

        // rb double-buffer: load ks=0 fragments up front, then each ks
        // prefetches ks+1's rb before issuing its mma stream.
        uint32_t rb[2][8][2];
        {
            const float* bp0 = Bs + btg * LDB + wn * 64 + bgq;
#pragma unroll
            for (int nj = 0; nj < 8; nj++) {
                rb[0][nj][0] = f2tf32u(bp0[nj * 8]);
                rb[0][nj][1] = f2tf32u(bp0[nj * 8 + 4 * LDB]);
            }
        }
#pragma unroll
        for (int ks = 0; ks < 4; ks++) {
            uint32_t ra[4][4];
#pragma unroll
            for (int mi = 0; mi < 4; mi++) {
                int row = wm * 64 + mi * 16 + lrow;
                int chunk = 2 * ks + lchv;
                uint32_t addr = aBase + (uint32_t)(row * 128 + ((chunk ^ (row & 7)) << 4));
                ldsm_x4(ra[mi], addr);
            }
            if (ks < 3) {   // prefetch rb for ks+1 into the other buffer
                const float* bpn = Bs + ((ks + 1) * 8 + btg) * LDB + wn * 64 + bgq;
#pragma unroll
                for (int nj = 0; nj < 8; nj++) {
                    rb[(ks + 1) & 1][nj][0] = f2tf32u(bpn[nj * 8]);
                    rb[(ks + 1) & 1][nj][1] = f2tf32u(bpn[nj * 8 + 4 * LDB]);
                }
            }
#pragma unroll
            for (int mi = 0; mi < 4; mi++)
#pragma unroll
                for (int nj = 0; nj < 8; nj++)
                    mma_tf32(acc[mi][nj], ra[mi], rb[ks & 1][nj]);
        }
        __syncthreads();
        if (i + NSTG < nIter) { prefetch(s, k0base + (i + NSTG) * BK); CP_COMMIT(); }
    }

    // ---- epilogue straight from registers ----
    int g  = lane >> 2;
    int tg = lane & 3;
#pragma unroll
    for (int mi = 0; mi < 4; mi++) {
#pragma unroll
        for (int half = 0; half < 2; half++) {
            int lr = mt * BM + wm * 64 + mi * 16 + half * 8 + g;
            if (lr >= count) continue;
            int slot = off0 + lr;
            if (PHASE == 0) {
                float* hrow = g_h + (size_t)slot * DFFN + n0;
#pragma unroll
                for (int nj = 0; nj < 8; nj++) {
                    int cl = wn * 64 + nj * 8 + tg * 2;
                    float2 v;
                    v.x = round_tf32(fmaxf(acc[mi][nj][half * 2 + 0] + sBias[cl],     0.f));
                    v.y = round_tf32(fmaxf(acc[mi][nj][half * 2 + 1] + sBias[cl + 1], 0.f));
                    *(float2*)(hrow + cl) = v;
                }
            } else {
                float gate = g_gate[slot];
                float* orow = out + (size_t)g_tok[slot] * DMODEL + n0;
#pragma unroll
                for (int nj = 0; nj < 8; nj++) {
                    int cl = wn * 64 + nj * 8 + tg * 2;
                    float v0 = (acc[mi][nj][half * 2 + 0] + sBias[cl])     * gate;
                    float v1 = (acc[mi][nj][half * 2 + 1] + sBias[cl + 1]) * gate;
                    asm volatile("red.global.add.f32 [%0], %1;" :: "l"(orow + cl),     "f"(v0) : "memory");
                    asm volatile("red.global.add.f32 [%0], %1;" :: "l"(orow + cl + 1), "f"(v1) : "memory");
                }
            }
        }
    }
}

// ---------------------------------------------------------------------------
extern "C" void kernel_launch(void* const* d_in, const int* in_sizes, int n_in,
                              void* d_out, int out_size) {
    const float* x     = (const float*)d_in[0];
    const float* noise = (const float*)d_in[1];
    const float* Wg    = (const float*)d_in[2];
    const float* bg    = (const float*)d_in[3];
    const float* Wn    = (const float*)d_in[4];
    const float* bn    = (const float*)d_in[5];
    const float* W1    = (const float*)d_in[6];
    const float* b1    = (const float*)d_in[7];
    const float* W2    = (const float*)d_in[8];
    const float* b2    = (const float*)d_in[9];
    float* out = (float*)d_out;

    cudaFuncSetAttribute(moe_gemm_mma<0>, cudaFuncAttributeMaxDynamicSharedMemorySize, SMEM_TOTAL);
    cudaFuncSetAttribute(moe_gemm_mma<1>, cudaFuncAttributeMaxDynamicSharedMemorySize, SMEM_TOTAL);

    router_kernel<<<(T_TOKENS * 32) / 256, 256>>>(x, noise, Wg, bg, Wn, bn);   // 1 (+x round, +offsets)
    scatter_kernel<<<T_TOKENS / 256, 256>>>();                                 // 2
    reset_out<<<1024, 256>>>((float4*)out, out_size / 4);                      // 3
    moe_gemm_mma<0><<<dim3(NEXP * MT_MAX, DFFN / BN, 1), 128, SMEM_TOTAL>>>(W1, b1, W2, b2, out);      // 4
    moe_gemm_mma<1><<<dim3(NEXP * MT_MAX, DMODEL / BN, KSL2), 128, SMEM_TOTAL>>>(W1, b1, W2, b2, out); // 5
}

// round 11
// speedup vs baseline: 1.0346x; 1.0001x over previous
#include <cuda_runtime.h>
#include <math.h>
#include <cstdint>
#include <stdint.h>

#define T_TOKENS 4096
#define DMODEL   1024
#define DFFN     4096
#define NEXP     8
#define TOPK     2
#define NSLOTS   (T_TOKENS * TOPK)
#define MT_MAX   64

// ---- scratch (__device__ globals; allocation-free rule) ----
__device__ float g_h[(size_t)NSLOTS * DFFN];        // 128 MiB (tf32-rounded)
__device__ float g_o[(size_t)NSLOTS * DMODEL];      // 32 MiB  per-slot fc2 output
__device__ float g_xr[(size_t)T_TOKENS * DMODEL];   // 16 MiB  (tf32-rounded x)
__device__ int   g_tok[NSLOTS];
__device__ float g_gate[NSLOTS];
__device__ int   g_pos[T_TOKENS * TOPK];            // token -> slot map
__device__ int   g_counts[NEXP];
__device__ int   g_cursor[NEXP];
__device__ int   g_off[NEXP + 1];
__device__ int   g_topi[T_TOKENS * TOPK];
__device__ float g_topg[T_TOKENS * TOPK];
__device__ int   g_done;

// ---------------------------------------------------------------------------
__device__ __forceinline__ uint32_t smem_u32(const void* p) {
    uint32_t a;
    asm("{ .reg .u64 t; cvta.to.shared.u64 t, %1; cvt.u32.u64 %0, t; }" : "=r"(a) : "l"(p));
    return a;
}
__device__ __forceinline__ void cp_async16u(uint32_t daddr, const float* src) {
    asm volatile("cp.async.cg.shared.global [%0], [%1], 16;\n" :: "r"(daddr), "l"(src));
}
#define CP_COMMIT() asm volatile("cp.async.commit_group;\n" ::: "memory")

__device__ __forceinline__ float round_tf32(float f) {
    uint32_t r;
    asm("cvt.rna.tf32.f32 %0, %1;" : "=r"(r) : "f"(f));
    return __uint_as_float(r);
}
__device__ __forceinline__ uint32_t f2tf32u(float f) {
    uint32_t r;
    asm("cvt.rna.tf32.f32 %0, %1;" : "=r"(r) : "f"(f));
    return r;
}

// ---------------------------------------------------------------------------
// One warp per token: noisy top-2 router. Also writes tf32-rounded x to g_xr.
// Last block computes expert offsets.
__global__ void router_kernel(const float* __restrict__ x, const float* __restrict__ noise,
                              const float* __restrict__ Wg, const float* __restrict__ bg,
                              const float* __restrict__ Wn, const float* __restrict__ bn) {
    int gw = (blockIdx.x * blockDim.x + threadIdx.x) >> 5;
    int lane = threadIdx.x & 31;
    if (gw < T_TOKENS) {
        const float* xr = x + (size_t)gw * DMODEL;
        float* xo = g_xr + (size_t)gw * DMODEL;
        float lg[NEXP], ln[NEXP];
#pragma unroll
        for (int e = 0; e < NEXP; e++) { lg[e] = 0.f; ln[e] = 0.f; }
        for (int d = lane; d < DMODEL; d += 32) {
            float xv = xr[d];
            xo[d] = round_tf32(xv);             // fused tf32 pre-round of x
#pragma unroll
            for (int e = 0; e < NEXP; e++) {
                lg[e] += xv * Wg[d * NEXP + e];
                ln[e] += xv * Wn[d * NEXP + e];
            }
        }
#pragma unroll
        for (int o = 16; o > 0; o >>= 1) {
#pragma unroll
            for (int e = 0; e < NEXP; e++) {
                lg[e] += __shfl_xor_sync(0xffffffffu, lg[e], o);
                ln[e] += __shfl_xor_sync(0xffffffffu, ln[e], o);
            }
        }
        if (lane == 0) {
            float nv[NEXP];
#pragma unroll
            for (int e = 0; e < NEXP; e++) {
                float nl = ln[e] + bn[e];
                float sp = (nl > 20.f) ? nl : log1pf(expf(nl));
                nv[e] = lg[e] + bg[e] + noise[gw * NEXP + e] * sp;
            }
            int i0 = 0;
#pragma unroll
            for (int e = 1; e < NEXP; e++) if (nv[e] > nv[i0]) i0 = e;
            int i1 = (i0 == 0) ? 1 : 0;
#pragma unroll
            for (int e = 0; e < NEXP; e++) if (e != i0 && nv[e] > nv[i1]) i1 = e;
            float e1 = expf(nv[i1] - nv[i0]);
            float s = 1.f + e1;
            g_topi[gw * 2]     = i0;  g_topg[gw * 2]     = 1.f / s;
            g_topi[gw * 2 + 1] = i1;  g_topg[gw * 2 + 1] = e1 / s;
            atomicAdd(&g_counts[i0], 1);
            atomicAdd(&g_counts[i1], 1);
        }
    }
    __syncthreads();
    if (threadIdx.x == 0) {
        __threadfence();
        int prev = atomicAdd(&g_done, 1);
        if (prev == (int)gridDim.x - 1) {
            g_done = 0;
            __threadfence();
            int acc = 0;
            for (int e = 0; e < NEXP; e++) {
                g_off[e] = acc; g_cursor[e] = acc;
                acc += g_counts[e];
                g_counts[e] = 0;        // ready for next replay
            }
            g_off[NEXP] = acc;
        }
    }
}

__global__ void scatter_kernel() {
    int t = blockIdx.x * blockDim.x + threadIdx.x;
    if (t >= T_TOKENS) return;
#pragma unroll
    for (int k = 0; k < TOPK; k++) {
        int e = g_topi[t * 2 + k];
        int pos = atomicAdd(&g_cursor[e], 1);
        g_tok[pos]  = t;
        g_gate[pos] = g_topg[t * 2 + k];
        g_pos[t * 2 + k] = pos;
    }
}

// out[t] = g_o[slot0] + g_o[slot1]  (vectorized float4)
__global__ void combine_kernel(float4* __restrict__ out) {
    int idx = blockIdx.x * blockDim.x + threadIdx.x;     // over T_TOKENS*256 float4s
    int t  = idx >> 8;
    int d4 = idx & 255;
    const float4* r0 = (const float4*)(g_o + (size_t)g_pos[t * 2]     * DMODEL) + d4;
    const float4* r1 = (const float4*)(g_o + (size_t)g_pos[t * 2 + 1] * DMODEL) + d4;
    float4 a = *r0, b = *r1;
    a.x += b.x; a.y += b.y; a.z += b.z; a.w += b.w;
    out[idx] = a;
}

// ---------------------------------------------------------------------------
// Grouped GEMM: mma.sync.m16n8k8 tf32.
//   4 warps, warp tile 64x64, CTA tile 128x128x32, NSTG=3 cp.async ring
//   (double-sync mainloop — measured best).
//   PHASE 0: g_h = relu(gather(xr) @ W1 + b1)       K=1024
//   PHASE 1: g_o[slot] = gate * (g_h @ W2 + b2)     K=4096 (plain stores)
#define BM 128
#define BN 128
#define BK 32
#define NSTG 3
#define LDB 136                               // floats; conflict-free B reads
#define A_BYTES   (BM * 128)                  // 16384 (128B swizzled rows)
#define B_BYTES   (BK * LDB * 4)              // 17408
#define STG_BYTES (A_BYTES + B_BYTES)         // 33792
#define SMEM_BIAS (NSTG * STG_BYTES)
#define SMEM_TOTAL (SMEM_BIAS + BN * 4)       // 101888 -> 2 CTAs/SM

__device__ __forceinline__ void mma_tf32(float* c, const uint32_t* a, const uint32_t* b) {
    asm volatile(
        "mma.sync.aligned.m16n8k8.row.col.f32.tf32.tf32.f32 "
        "{%0,%1,%2,%3}, {%4,%5,%6,%7}, {%8,%9}, {%0,%1,%2,%3};"
        : "+f"(c[0]), "+f"(c[1]), "+f"(c[2]), "+f"(c[3])
        : "r"(a[0]), "r"(a[1]), "r"(a[2]), "r"(a[3]), "r"(b[0]), "r"(b[1]));
}
__device__ __forceinline__ void ldsm_x4(uint32_t* r, uint32_t addr) {
    asm volatile("ldmatrix.sync.aligned.m8n8.x4.shared.b16 {%0,%1,%2,%3}, [%4];"
                 : "=r"(r[0]), "=r"(r[1]), "=r"(r[2]), "=r"(r[3]) : "r"(addr));
}

template <int PHASE>
__global__ __launch_bounds__(128, 2)
void moe_gemm_mma(const float* __restrict__ W1, const float* __restrict__ b1,
                  const float* __restrict__ W2, const float* __restrict__ b2) {
    constexpr int K  = PHASE ? DFFN : DMODEL;
    constexpr int NN = PHASE ? DMODEL : DFFN;

    int e  = blockIdx.x >> 6;
    int mt = blockIdx.x & (MT_MAX - 1);
    int off0  = g_off[e];
    int count = g_off[e + 1] - off0;
    if (mt * BM >= count) return;
    int n0 = blockIdx.y * BN;

    extern __shared__ char smem[];
    uint32_t sb = smem_u32(smem);
    float* sBias = (float*)(smem + SMEM_BIAS);

    int tid  = threadIdx.x;
    int wid  = tid >> 5;
    int lane = tid & 31;
    int wm = wid & 1;              // 2 warps along M (64 rows)
    int wn = wid >> 1;             // 2 warps along N (64 cols)

    const float* bias = PHASE ? (b2 + e * DMODEL) : (b1 + e * DFFN);
    sBias[tid] = bias[n0 + tid];   // blockDim == BN == 128

    const float* Bsrc = PHASE ? (W2 + (size_t)e * DFFN * DMODEL)
                              : (W1 + (size_t)e * DMODEL * DFFN);

    // ---- per-thread cp.async assignments (128 threads) ----
    int ac = tid & 7;
    const float* aP[8];
    uint32_t aDst[8];
#pragma unroll
    for (int i = 0; i < 8; i++) {
        int idx = tid + i * 128;
        int row = idx >> 3;
        int lr = mt * BM + row;
        if (lr >= count) lr = count - 1;
        int slot = off0 + lr;
        const float* base = PHASE ? (g_h + (size_t)slot * DFFN)
                                  : (g_xr + (size_t)g_tok[slot] * DMODEL);
        aP[i]  = base + ac * 4;
        aDst[i] = (uint32_t)(row * 128 + ((ac ^ (row & 7)) << 4));
    }

    const int nIter = K / BK;

    auto prefetch = [&](int s, int k0) {
        uint32_t ab = sb + s * STG_BYTES;
        uint32_t bb = ab + A_BYTES;
#pragma unroll
        for (int i = 0; i < 8; i++)
            cp_async16u(ab + aDst[i], aP[i] + k0);
#pragma unroll
        for (int i = 0; i < 8; i++) {            // B: 32 k-rows x 32 chunks
            int idx = tid + i * 128;
            int kr = idx >> 5, c = idx & 31;
            cp_async16u(bb + (uint32_t)(kr * (LDB * 4) + c * 16),
                        Bsrc + (size_t)(k0 + kr) * NN + n0 + c * 4);
        }
    };

#pragma unroll
    for (int p = 0; p < NSTG; p++) { prefetch(p, p * BK); CP_COMMIT(); }

    float acc[4][8][4];
#pragma unroll
    for (int mi = 0; mi < 4; mi++)
#pragma unroll
        for (int nj = 0; nj < 8; nj++)
#pragma unroll
            for (int r = 0; r < 4; r++) acc[mi][nj][r] = 0.f;

    // per-lane fragment address components
    int lrow = (lane & 7) + (((lane >> 3) & 1) << 3);   // 0..15
    int lchv = lane >> 4;                                // chunk parity
    int btg  = lane & 3;                                 // B k within quad
    int bgq  = lane >> 2;                                // B n within n8

    for (int i = 0; i < nIter; i++) {
        int rem = nIter - 1 - i;
        if (rem >= NSTG - 1)      asm volatile("cp.async.wait_group 2;\n" ::: "memory");
        else if (rem == 1)        asm volatile("cp.async.wait_group 1;\n" ::: "memory");
        else                      asm volatile("cp.async.wait_group 0;\n" ::: "memory");
        __syncthreads();
        int s = i % NSTG;
        uint32_t aBase = sb + s * STG_BYTES;
        const float* Bs = (const float*)(smem + s * STG_BYTES + A_BYTES);

#pragma unroll
        for (int ks = 0; ks < 4; ks++) {
            uint32_t ra[4][4];
#pragma unroll
            for (int mi = 0; mi < 4; mi++) {
                int row = wm * 64 + mi * 16 + lrow;
                int chunk = 2 * ks + lchv;
                uint32_t addr = aBase + (uint32_t)(row * 128 + ((chunk ^ (row & 7)) << 4));
                ldsm_x4(ra[mi], addr);
            }
            uint32_t rb[8][2];
            const float* bp = Bs + (ks * 8 + btg) * LDB + wn * 64 + bgq;
#pragma unroll
            for (int nj = 0; nj < 8; nj++) {
                rb[nj][0] = f2tf32u(bp[nj * 8]);
                rb[nj][1] = f2tf32u(bp[nj * 8 + 4 * LDB]);
            }
#pragma unroll
            for (int mi = 0; mi < 4; mi++)
#pragma unroll
                for (int nj = 0; nj < 8; nj++)
                    mma_tf32(acc[mi][nj], ra[mi], rb[nj]);
        }
        __syncthreads();
        if (i + NSTG < nIter) { prefetch(s, (i + NSTG) * BK); CP_COMMIT(); }
    }

    // ---- epilogue straight from registers (plain stores both phases) ----
    int g  = lane >> 2;
    int tg = lane & 3;
#pragma unroll
    for (int mi = 0; mi < 4; mi++) {
#pragma unroll
        for (int half = 0; half < 2; half++) {
            int lr = mt * BM + wm * 64 + mi * 16 + half * 8 + g;
            if (lr >= count) continue;
            int slot = off0 + lr;
            if (PHASE == 0) {
                float* hrow = g_h + (size_t)slot * DFFN + n0;
#pragma unroll
                for (int nj = 0; nj < 8; nj++) {
                    int cl = wn * 64 + nj * 8 + tg * 2;
                    float2 v;
                    v.x = round_tf32(fmaxf(acc[mi][nj][half * 2 + 0] + sBias[cl],     0.f));
                    v.y = round_tf32(fmaxf(acc[mi][nj][half * 2 + 1] + sBias[cl + 1], 0.f));
                    *(float2*)(hrow + cl) = v;
                }
            } else {
                float gate = g_gate[slot];
                float* orow = g_o + (size_t)slot * DMODEL + n0;
#pragma unroll
                for (int nj = 0; nj < 8; nj++) {
                    int cl = wn * 64 + nj * 8 + tg * 2;
                    float2 v;
                    v.x = (acc[mi][nj][half * 2 + 0] + sBias[cl])     * gate;
                    v.y = (acc[mi][nj][half * 2 + 1] + sBias[cl + 1]) * gate;
                    *(float2*)(orow + cl) = v;
                }
            }
        }
    }
}

// ---------------------------------------------------------------------------
extern "C" void kernel_launch(void* const* d_in, const int* in_sizes, int n_in,
                              void* d_out, int out_size) {
    const float* x     = (const float*)d_in[0];
    const float* noise = (const float*)d_in[1];
    const float* Wg    = (const float*)d_in[2];
    const float* bg    = (const float*)d_in[3];
    const float* Wn    = (const float*)d_in[4];
    const float* bn    = (const float*)d_in[5];
    const float* W1    = (const float*)d_in[6];
    const float* b1    = (const float*)d_in[7];
    const float* W2    = (const float*)d_in[8];
    const float* b2    = (const float*)d_in[9];
    float* out = (float*)d_out;

    cudaFuncSetAttribute(moe_gemm_mma<0>, cudaFuncAttributeMaxDynamicSharedMemorySize, SMEM_TOTAL);
    cudaFuncSetAttribute(moe_gemm_mma<1>, cudaFuncAttributeMaxDynamicSharedMemorySize, SMEM_TOTAL);

    router_kernel<<<(T_TOKENS * 32) / 256, 256>>>(x, noise, Wg, bg, Wn, bn);   // 1 (+x round, +offsets)
    scatter_kernel<<<T_TOKENS / 256, 256>>>();                                 // 2 (+g_pos)
    moe_gemm_mma<0><<<dim3(NEXP * MT_MAX, DFFN / BN), 128, SMEM_TOTAL>>>(W1, b1, W2, b2);   // 3
    moe_gemm_mma<1><<<dim3(NEXP * MT_MAX, DMODEL / BN), 128, SMEM_TOTAL>>>(W1, b1, W2, b2); // 4
    combine_kernel<<<(T_TOKENS * 256) / 256, 256>>>((float4*)out);             // 5
}